// round 1
// baseline (speedup 1.0000x reference)
#include <cuda_runtime.h>
#include <cstdint>
#include <math.h>

// ---------------- problem constants ----------------
#define FSR    44100.0
#define NS     131072            // samples per channel
#define NCHAN  32                // 4*8 channels
#define CHUNK  256               // samples per chunk (biquad decomposition)
#define NCH    (NS/CHUNK)        // 512 chunks per channel

// ---------------- device scratch (static, no allocs) ----------------
__device__ float g_bufA[NCHAN * NS];   // 16 MB
__device__ float g_bufB[NCHAN * NS];   // 16 MB
__device__ float g_gc  [NCHAN * NS];   // 16 MB
__device__ float2 g_state[6][NCH * NCHAN];
__device__ float2 g_start[6][NCH * NCHAN];

struct ChParams {
    float b0[6], b1[6], b2[6], a1[6], a2[6];
    float gain;
    float thr, qr, k2, kk, inv2k;      // compressor static curve
    float aa, ar, ka, kr, sigma, mk;   // envelope
    float cth, sth;                    // pan
};
__device__ ChParams g_par[NCHAN];

__device__ const float PLO[26] = {-24.f,-20.f,20.f,0.1f,-20.f,80.f,0.1f,-20.f,200.f,0.1f,-20.f,500.f,0.1f,
                                  -20.f,1000.f,0.1f,-20.f,4000.f,0.1f,-60.f,1.f,1.f,10.f,0.1f,0.f,0.f};
__device__ const float PHI[26] = {24.f,20.f,2000.f,6.f,20.f,2000.f,6.f,20.f,4000.f,6.f,20.f,8000.f,6.f,
                                  20.f,12000.f,6.f,20.f,18000.f,6.f,0.f,10.f,100.f,1000.f,24.f,12.f,1.f};

// ---------------- coefficient setup (32 threads) ----------------
__device__ inline void store_norm(ChParams& P, int s, double b0d, double b1d, double b2d,
                                  double a0d, double a1d, double a2d) {
    P.b0[s] = (float)(b0d / a0d);
    P.b1[s] = (float)(b1d / a0d);
    P.b2[s] = (float)(b2d / a0d);
    P.a1[s] = (float)(a1d / a0d);
    P.a2[s] = (float)(a2d / a0d);
}

__device__ inline void shelf_coeffs(ChParams& P, int s, double g, double f, double q, double sgn) {
    double A  = pow(10.0, g / 40.0);
    double w0 = 2.0 * M_PI * f / FSR;
    double cw = cos(w0), sw = sin(w0);
    double alpha = sw / (2.0 * q);
    double s2 = 2.0 * sqrt(A) * alpha;
    double b0 = A * (A + 1.0 - sgn * (A - 1.0) * cw + s2);
    double b1 = sgn * 2.0 * A * (A - 1.0 - sgn * (A + 1.0) * cw);
    double b2 = A * (A + 1.0 - sgn * (A - 1.0) * cw - s2);
    double a0 = A + 1.0 + sgn * (A - 1.0) * cw + s2;
    double a1 = -sgn * 2.0 * (A - 1.0 + sgn * (A + 1.0) * cw);
    double a2 = A + 1.0 + sgn * (A - 1.0) * cw - s2;
    store_norm(P, s, b0, b1, b2, a0, a1, a2);
}

__device__ inline void peak_coeffs(ChParams& P, int s, double g, double f, double q) {
    double A  = pow(10.0, g / 40.0);
    double w0 = 2.0 * M_PI * f / FSR;
    double cw = cos(w0), sw = sin(w0);
    double alpha = sw / (2.0 * q);
    double b0 = 1.0 + alpha * A;
    double b1 = -2.0 * cw;
    double b2 = 1.0 - alpha * A;
    double a0 = 1.0 + alpha / A;
    double a1 = -2.0 * cw;
    double a2 = 1.0 - alpha / A;
    store_norm(P, s, b0, b1, b2, a0, a1, a2);
}

__global__ void k_coef(const float* __restrict__ mp) {
    int c = threadIdx.x;
    if (c >= NCHAN) return;
    double p[26];
#pragma unroll
    for (int i = 0; i < 26; i++) {
        double lo = PLO[i], hi = PHI[i];
        p[i] = (double)mp[c * 26 + i] * (hi - lo) + lo;
    }
    ChParams P;
    P.gain = (float)pow(10.0, p[0] / 20.0);
    shelf_coeffs(P, 0, p[1],  p[2],  p[3],  +1.0);
    peak_coeffs (P, 1, p[4],  p[5],  p[6]);
    peak_coeffs (P, 2, p[7],  p[8],  p[9]);
    peak_coeffs (P, 3, p[10], p[11], p[12]);
    peak_coeffs (P, 4, p[13], p[14], p[15]);
    shelf_coeffs(P, 5, p[16], p[17], p[18], -1.0);

    P.thr  = (float)p[19];
    P.qr   = (float)(1.0 / p[20] - 1.0);
    P.kk   = (float)p[23];
    P.k2   = (float)(p[23] * 0.5);
    P.inv2k= (float)(1.0 / (2.0 * p[23]));
    float aa = (float)exp(-1.0 / (FSR * p[21] * 0.001));
    float ar = (float)exp(-1.0 / (FSR * p[22] * 0.001));
    // replicate reference fp32 rounding of (1 - alpha) to match steady-state bias
    float omaa = 1.0f - aa;
    float omar = 1.0f - ar;
    float sg = (aa >= ar) ? 1.0f : -1.0f;
    P.aa = aa; P.ar = ar;
    P.sigma = sg; P.ka = sg * omaa; P.kr = sg * omar;
    P.mk = (float)p[24];
    double th = p[25] * (M_PI * 0.5);
    P.cth = (float)cos(th);
    P.sth = (float)sin(th);
    g_par[c] = P;
}

// ---------------- transpose [c][t] -> [t][c] with input gain ----------------
__global__ void k_transpose(const float* __restrict__ tracks) {
    __shared__ float tile[32][33];
    int t0 = blockIdx.x * 32;
    int tx = threadIdx.x, ty = threadIdx.y;   // (32, 8)
#pragma unroll
    for (int i = 0; i < 4; i++) {
        int row = ty + i * 8;                 // channel
        tile[row][tx] = tracks[(size_t)row * NS + t0 + tx];
    }
    __syncthreads();
#pragma unroll
    for (int i = 0; i < 4; i++) {
        int row = ty + i * 8;                 // time offset within tile
        g_bufA[(size_t)(t0 + row) * NCHAN + tx] = tile[tx][row] * g_par[tx].gain;
    }
}

// ---------------- biquad chunk kernels ----------------
// pass 1 of stage 0: zero-init states only
__global__ void k_pass1_0() {
    int c = threadIdx.x;
    int k = blockIdx.x * blockDim.y + threadIdx.y;
    const ChParams& P = g_par[c];
    float b0 = P.b0[0], b1 = P.b1[0], b2 = P.b2[0], a1 = P.a1[0], a2 = P.a2[0];
    float s1 = 0.f, s2 = 0.f;
    const float* in = g_bufA + (size_t)k * CHUNK * NCHAN + c;
#pragma unroll 16
    for (int t = 0; t < CHUNK; t++) {
        float x = in[(size_t)t * NCHAN];
        float y = fmaf(b0, x, s1);
        s1 = fmaf(-a1, y, fmaf(b1, x, s2));
        s2 = fmaf(-a2, y, b2 * x);
    }
    g_state[0][k * NCHAN + c] = make_float2(s1, s2);
}

// per-channel scan: start states for chunks of stage s
__global__ void k_scan(int s) {
    int c = threadIdx.x;
    if (c >= NCHAN) return;
    float a1 = g_par[c].a1[s], a2 = g_par[c].a2[s];
    double m00 = -(double)a1, m01 = 1.0, m10 = -(double)a2, m11 = 0.0;
#pragma unroll
    for (int i = 0; i < 8; i++) {  // (2x2)^(2^8) -> A^256
        double n00 = m00*m00 + m01*m10, n01 = m00*m01 + m01*m11;
        double n10 = m10*m00 + m11*m10, n11 = m10*m01 + m11*m11;
        m00 = n00; m01 = n01; m10 = n10; m11 = n11;
    }
    float f00 = (float)m00, f01 = (float)m01, f10 = (float)m10, f11 = (float)m11;
    float s1 = 0.f, s2 = 0.f;
    for (int k = 0; k < NCH; k++) {
        g_start[s][k * NCHAN + c] = make_float2(s1, s2);
        float2 d = g_state[s][k * NCHAN + c];
        float n1 = fmaf(f00, s1, fmaf(f01, s2, d.x));
        float n2 = fmaf(f10, s1, fmaf(f11, s2, d.y));
        s1 = n1; s2 = n2;
    }
}

// pass2 of stage s fused with pass1 of stage s+1
__global__ void k_fuse(int s, const float* __restrict__ in, float* __restrict__ out) {
    int c = threadIdx.x;
    int k = blockIdx.x * blockDim.y + threadIdx.y;
    const ChParams& P = g_par[c];
    float cb0 = P.b0[s],   cb1 = P.b1[s],   cb2 = P.b2[s],   ca1 = P.a1[s],   ca2 = P.a2[s];
    float nb0 = P.b0[s+1], nb1 = P.b1[s+1], nb2 = P.b2[s+1], na1 = P.a1[s+1], na2 = P.a2[s+1];
    float2 S = g_start[s][k * NCHAN + c];
    float s1 = S.x, s2 = S.y, z1 = 0.f, z2 = 0.f;
    const float* ip = in  + (size_t)k * CHUNK * NCHAN + c;
    float*       op = out + (size_t)k * CHUNK * NCHAN + c;
#pragma unroll 16
    for (int t = 0; t < CHUNK; t++) {
        float x = ip[(size_t)t * NCHAN];
        float y = fmaf(cb0, x, s1);
        s1 = fmaf(-ca1, y, fmaf(cb1, x, s2));
        s2 = fmaf(-ca2, y, cb2 * x);
        op[(size_t)t * NCHAN] = y;
        float w = fmaf(nb0, y, z1);
        z1 = fmaf(-na1, w, fmaf(nb1, y, z2));
        z2 = fmaf(-na2, w, nb2 * y);
    }
    g_state[s + 1][k * NCHAN + c] = make_float2(z1, z2);
}

// stage 5 pass2 + compressor static gain curve
__global__ void k_last(const float* __restrict__ in, float* __restrict__ outy) {
    int c = threadIdx.x;
    int k = blockIdx.x * blockDim.y + threadIdx.y;
    const ChParams& P = g_par[c];
    float b0 = P.b0[5], b1 = P.b1[5], b2 = P.b2[5], a1 = P.a1[5], a2 = P.a2[5];
    float thr = P.thr, qr = P.qr, k2 = P.k2, kk = P.kk, inv2k = P.inv2k;
    float2 S = g_start[5][k * NCHAN + c];
    float s1 = S.x, s2 = S.y;
    const float* ip = in   + (size_t)k * CHUNK * NCHAN + c;
    float*       op = outy + (size_t)k * CHUNK * NCHAN + c;
    float*       gp = g_gc + (size_t)k * CHUNK * NCHAN + c;
#pragma unroll 8
    for (int t = 0; t < CHUNK; t++) {
        float x = ip[(size_t)t * NCHAN];
        float y = fmaf(b0, x, s1);
        s1 = fmaf(-a1, y, fmaf(b1, x, s2));
        s2 = fmaf(-a2, y, b2 * x);
        op[(size_t)t * NCHAN] = y;
        float v   = fmaxf(fabsf(y), 1e-8f);
        float xdb = 6.0205999132796239f * __log2f(v);   // 20*log10(v)
        float d   = xdb - thr;
        float t1  = d + k2;
        float mid = qr * t1 * t1 * inv2k;
        float hi  = qr * d;
        float gcv = (t1 <= 0.f) ? 0.f : ((t1 >= kk) ? hi : mid);
        gp[(size_t)t * NCHAN] = gcv;
    }
}

// ---------------- serial envelope: one warp, lane = channel ----------------
__global__ void __launch_bounds__(32, 1) k_env() {
    int c = threadIdx.x;
    const ChParams& P = g_par[c];
    float aa = P.aa, ar = P.ar, ka = P.ka, kr = P.kr;
    float h = 0.f;
    const int G = 32, NG = NS / G;
    float cur[G], nxt[G];
    const float* gp = g_gc + c;
    float* hp = g_bufB + c;
#pragma unroll
    for (int j = 0; j < G; j++) cur[j] = gp[(size_t)j * NCHAN];
    for (int grp = 0; grp < NG; grp++) {
        if (grp + 1 < NG) {
            const float* np = gp + (size_t)(grp + 1) * G * NCHAN;
#pragma unroll
            for (int j = 0; j < G; j++) nxt[j] = np[(size_t)j * NCHAN];
        }
#pragma unroll
        for (int j = 0; j < G; j++) {
            float gc = cur[j];
            float fa = fmaf(aa, h, ka * gc);
            float fr = fmaf(ar, h, kr * gc);
            h = fmaxf(fa, fr);                 // exact switched one-pole (sign-folded)
            hp[(size_t)(grp * G + j) * NCHAN] = h;
        }
#pragma unroll
        for (int j = 0; j < G; j++) cur[j] = nxt[j];
    }
}

// ---------------- apply gain, pan, sum over tracks ----------------
__global__ void k_mix(float* __restrict__ out) {
    int t = blockIdx.x * blockDim.x + threadIdx.x;
    int b = blockIdx.y;
    const float* y = g_bufA + (size_t)t * NCHAN + b * 8;
    const float* h = g_bufB + (size_t)t * NCHAN + b * 8;
    float sl = 0.f, sr = 0.f;
#pragma unroll
    for (int j = 0; j < 8; j++) {
        int c = b * 8 + j;
        const ChParams& P = g_par[c];
        float gdb = fmaf(P.sigma, h[j], P.mk);
        float gl  = exp2f(gdb * 0.16609640474436813f);  // 10^(gdb/20)
        float v   = y[j] * gl;
        sl = fmaf(P.cth, v, sl);
        sr = fmaf(P.sth, v, sr);
    }
    out[(size_t)(b * 2 + 0) * NS + t] = sl;
    out[(size_t)(b * 2 + 1) * NS + t] = sr;
}

// ---------------- launch ----------------
extern "C" void kernel_launch(void* const* d_in, const int* in_sizes, int n_in,
                              void* d_out, int out_size) {
    const float* tracks = (const float*)d_in[0];
    const float* mparam = (const float*)d_in[1];
    float* out = (float*)d_out;

    float *bufA, *bufB;
    cudaGetSymbolAddress((void**)&bufA, g_bufA);
    cudaGetSymbolAddress((void**)&bufB, g_bufB);

    dim3 pb(32, 8);
    int  pg = NCH / 8;   // 64 blocks

    k_coef<<<1, 32>>>(mparam);
    k_transpose<<<NS / 32, dim3(32, 8)>>>(tracks);
    k_pass1_0<<<pg, pb>>>();
    k_scan<<<1, 32>>>(0);
    k_fuse<<<pg, pb>>>(0, bufA, bufB);
    k_scan<<<1, 32>>>(1);
    k_fuse<<<pg, pb>>>(1, bufB, bufA);
    k_scan<<<1, 32>>>(2);
    k_fuse<<<pg, pb>>>(2, bufA, bufB);
    k_scan<<<1, 32>>>(3);
    k_fuse<<<pg, pb>>>(3, bufB, bufA);
    k_scan<<<1, 32>>>(4);
    k_fuse<<<pg, pb>>>(4, bufA, bufB);
    k_scan<<<1, 32>>>(5);
    k_last<<<pg, pb>>>(bufB, bufA);     // y5 -> bufA, gc -> g_gc
    k_env<<<1, 32>>>();                 // h  -> bufB
    k_mix<<<dim3(NS / 256, 4), 256>>>(out);
}

// round 2
// speedup vs baseline: 1.6279x; 1.6279x over previous
#include <cuda_runtime.h>
#include <cstdint>
#include <math.h>

// ---------------- problem constants ----------------
#define FSR    44100.0
#define NS     131072            // samples per channel
#define NCHAN  32                // 4*8 channels
#define CHUNK  128               // samples per chunk (biquad decomposition)
#define NCH    (NS/CHUNK)        // 1024 chunks per channel
#define EU     16                // envelope block size
#define ENB    (NS/EU)           // 8192 envelope blocks
#define NLINES 17                // EU+1 slope classes
#define LPAD   20                // padded to 5 float4

// ---------------- device scratch (static, no allocs) ----------------
__device__ float g_bufA[NCHAN * NS];        // 16 MB
__device__ float g_bufB[NCHAN * NS];        // 16 MB
__device__ float g_gc  [NCHAN * NS];        // 16 MB
__device__ float g_int [ENB * NCHAN * LPAD];// ~21 MB: envelope intercepts
__device__ float g_hb  [ENB * NCHAN];       // 1 MB : envelope block-boundary h
__device__ float g_slope[NCHAN][NLINES];
__device__ float2 g_state[6][NCH * NCHAN];
__device__ float2 g_start[6][NCH * NCHAN];

struct ChParams {
    float b0[6], b1[6], b2[6], a1[6], a2[6];
    float gain;
    float thr, qr, k2, kk, inv2k;      // compressor static curve
    float aa, ar, ka, kr, sigma, mk;   // envelope
    float cth, sth;                    // pan
};
__device__ ChParams g_par[NCHAN];

__device__ const float PLO[26] = {-24.f,-20.f,20.f,0.1f,-20.f,80.f,0.1f,-20.f,200.f,0.1f,-20.f,500.f,0.1f,
                                  -20.f,1000.f,0.1f,-20.f,4000.f,0.1f,-60.f,1.f,1.f,10.f,0.1f,0.f,0.f};
__device__ const float PHI[26] = {24.f,20.f,2000.f,6.f,20.f,2000.f,6.f,20.f,4000.f,6.f,20.f,8000.f,6.f,
                                  20.f,12000.f,6.f,20.f,18000.f,6.f,0.f,10.f,100.f,1000.f,24.f,12.f,1.f};

// ---------------- coefficient setup (32 threads) ----------------
__device__ inline void store_norm(ChParams& P, int s, double b0d, double b1d, double b2d,
                                  double a0d, double a1d, double a2d) {
    P.b0[s] = (float)(b0d / a0d);
    P.b1[s] = (float)(b1d / a0d);
    P.b2[s] = (float)(b2d / a0d);
    P.a1[s] = (float)(a1d / a0d);
    P.a2[s] = (float)(a2d / a0d);
}

__device__ inline void shelf_coeffs(ChParams& P, int s, double g, double f, double q, double sgn) {
    double A  = pow(10.0, g / 40.0);
    double w0 = 2.0 * M_PI * f / FSR;
    double cw = cos(w0), sw = sin(w0);
    double alpha = sw / (2.0 * q);
    double s2 = 2.0 * sqrt(A) * alpha;
    double b0 = A * (A + 1.0 - sgn * (A - 1.0) * cw + s2);
    double b1 = sgn * 2.0 * A * (A - 1.0 - sgn * (A + 1.0) * cw);
    double b2 = A * (A + 1.0 - sgn * (A - 1.0) * cw - s2);
    double a0 = A + 1.0 + sgn * (A - 1.0) * cw + s2;
    double a1 = -sgn * 2.0 * (A - 1.0 + sgn * (A + 1.0) * cw);
    double a2 = A + 1.0 + sgn * (A - 1.0) * cw - s2;
    store_norm(P, s, b0, b1, b2, a0, a1, a2);
}

__device__ inline void peak_coeffs(ChParams& P, int s, double g, double f, double q) {
    double A  = pow(10.0, g / 40.0);
    double w0 = 2.0 * M_PI * f / FSR;
    double cw = cos(w0), sw = sin(w0);
    double alpha = sw / (2.0 * q);
    double b0 = 1.0 + alpha * A;
    double b1 = -2.0 * cw;
    double b2 = 1.0 - alpha * A;
    double a0 = 1.0 + alpha / A;
    double a1 = -2.0 * cw;
    double a2 = 1.0 - alpha / A;
    store_norm(P, s, b0, b1, b2, a0, a1, a2);
}

__global__ void k_coef(const float* __restrict__ mp) {
    int c = threadIdx.x;
    if (c >= NCHAN) return;
    double p[26];
#pragma unroll
    for (int i = 0; i < 26; i++) {
        double lo = PLO[i], hi = PHI[i];
        p[i] = (double)mp[c * 26 + i] * (hi - lo) + lo;
    }
    ChParams P;
    P.gain = (float)pow(10.0, p[0] / 20.0);
    shelf_coeffs(P, 0, p[1],  p[2],  p[3],  +1.0);
    peak_coeffs (P, 1, p[4],  p[5],  p[6]);
    peak_coeffs (P, 2, p[7],  p[8],  p[9]);
    peak_coeffs (P, 3, p[10], p[11], p[12]);
    peak_coeffs (P, 4, p[13], p[14], p[15]);
    shelf_coeffs(P, 5, p[16], p[17], p[18], -1.0);

    P.thr  = (float)p[19];
    P.qr   = (float)(1.0 / p[20] - 1.0);
    P.kk   = (float)p[23];
    P.k2   = (float)(p[23] * 0.5);
    P.inv2k= (float)(1.0 / (2.0 * p[23]));
    float aa = (float)exp(-1.0 / (FSR * p[21] * 0.001));
    float ar = (float)exp(-1.0 / (FSR * p[22] * 0.001));
    // replicate reference fp32 rounding of (1 - alpha)
    float omaa = 1.0f - aa;
    float omar = 1.0f - ar;
    float sg = (aa >= ar) ? 1.0f : -1.0f;
    P.aa = aa; P.ar = ar;
    P.sigma = sg; P.ka = sg * omaa; P.kr = sg * omar;
    P.mk = (float)p[24];
    double th = p[25] * (M_PI * 0.5);
    P.cth = (float)cos(th);
    P.sth = (float)sin(th);
    g_par[c] = P;
    // envelope slope classes: aa^i * ar^(EU-i)
#pragma unroll
    for (int i = 0; i < NLINES; i++)
        g_slope[c][i] = (float)(pow((double)aa, (double)i) * pow((double)ar, (double)(EU - i)));
}

// ---------------- transpose [c][t] -> [t][c] with input gain ----------------
__global__ void k_transpose(const float* __restrict__ tracks) {
    __shared__ float tile[32][33];
    int t0 = blockIdx.x * 32;
    int tx = threadIdx.x, ty = threadIdx.y;   // (32, 8)
#pragma unroll
    for (int i = 0; i < 4; i++) {
        int row = ty + i * 8;                 // channel
        tile[row][tx] = tracks[(size_t)row * NS + t0 + tx];
    }
    __syncthreads();
#pragma unroll
    for (int i = 0; i < 4; i++) {
        int row = ty + i * 8;                 // time offset within tile
        g_bufA[(size_t)(t0 + row) * NCHAN + tx] = tile[tx][row] * g_par[tx].gain;
    }
}

// ---------------- biquad chunk kernels ----------------
__global__ void k_pass1_0() {
    int c = threadIdx.x;
    int k = blockIdx.x * blockDim.y + threadIdx.y;
    const ChParams& P = g_par[c];
    float b0 = P.b0[0], b1 = P.b1[0], b2 = P.b2[0], a1 = P.a1[0], a2 = P.a2[0];
    float s1 = 0.f, s2 = 0.f;
    const float* in = g_bufA + (size_t)k * CHUNK * NCHAN + c;
#pragma unroll 16
    for (int t = 0; t < CHUNK; t++) {
        float x = in[(size_t)t * NCHAN];
        float y = fmaf(b0, x, s1);
        s1 = fmaf(-a1, y, fmaf(b1, x, s2));
        s2 = fmaf(-a2, y, b2 * x);
    }
    g_state[0][k * NCHAN + c] = make_float2(s1, s2);
}

// per-channel scan over chunk states (batched loads, double-buffered)
__global__ void __launch_bounds__(32, 1) k_scan(int s) {
    int c = threadIdx.x;
    if (c >= NCHAN) return;
    float a1 = g_par[c].a1[s], a2 = g_par[c].a2[s];
    double m00 = -(double)a1, m01 = 1.0, m10 = -(double)a2, m11 = 0.0;
#pragma unroll
    for (int i = 0; i < 7; i++) {  // (2x2)^(2^7) -> A^128
        double n00 = m00*m00 + m01*m10, n01 = m00*m01 + m01*m11;
        double n10 = m10*m00 + m11*m10, n11 = m10*m01 + m11*m11;
        m00 = n00; m01 = n01; m10 = n10; m11 = n11;
    }
    float f00 = (float)m00, f01 = (float)m01, f10 = (float)m10, f11 = (float)m11;
    float s1 = 0.f, s2 = 0.f;
    const int B = 32;
    float2 cur[B], nxt[B];
    const float2* st = g_state[s];
    float2*       sr = g_start[s];
#pragma unroll
    for (int j = 0; j < B; j++) cur[j] = st[j * NCHAN + c];
    for (int kb = 0; kb < NCH; kb += B) {
        if (kb + B < NCH) {
#pragma unroll
            for (int j = 0; j < B; j++) nxt[j] = st[(kb + B + j) * NCHAN + c];
        }
#pragma unroll
        for (int j = 0; j < B; j++) {
            sr[(kb + j) * NCHAN + c] = make_float2(s1, s2);
            float2 d = cur[j];
            float n1 = fmaf(f00, s1, fmaf(f01, s2, d.x));
            float n2 = fmaf(f10, s1, fmaf(f11, s2, d.y));
            s1 = n1; s2 = n2;
        }
#pragma unroll
        for (int j = 0; j < B; j++) cur[j] = nxt[j];
    }
}

// pass2 of stage s fused with pass1 of stage s+1
__global__ void k_fuse(int s, const float* __restrict__ in, float* __restrict__ out) {
    int c = threadIdx.x;
    int k = blockIdx.x * blockDim.y + threadIdx.y;
    const ChParams& P = g_par[c];
    float cb0 = P.b0[s],   cb1 = P.b1[s],   cb2 = P.b2[s],   ca1 = P.a1[s],   ca2 = P.a2[s];
    float nb0 = P.b0[s+1], nb1 = P.b1[s+1], nb2 = P.b2[s+1], na1 = P.a1[s+1], na2 = P.a2[s+1];
    float2 S = g_start[s][k * NCHAN + c];
    float s1 = S.x, s2 = S.y, z1 = 0.f, z2 = 0.f;
    const float* ip = in  + (size_t)k * CHUNK * NCHAN + c;
    float*       op = out + (size_t)k * CHUNK * NCHAN + c;
#pragma unroll 16
    for (int t = 0; t < CHUNK; t++) {
        float x = ip[(size_t)t * NCHAN];
        float y = fmaf(cb0, x, s1);
        s1 = fmaf(-ca1, y, fmaf(cb1, x, s2));
        s2 = fmaf(-ca2, y, cb2 * x);
        op[(size_t)t * NCHAN] = y;
        float w = fmaf(nb0, y, z1);
        z1 = fmaf(-na1, w, fmaf(nb1, y, z2));
        z2 = fmaf(-na2, w, nb2 * y);
    }
    g_state[s + 1][k * NCHAN + c] = make_float2(z1, z2);
}

// stage 5 pass2 + compressor static gain curve
__global__ void k_last(const float* __restrict__ in, float* __restrict__ outy) {
    int c = threadIdx.x;
    int k = blockIdx.x * blockDim.y + threadIdx.y;
    const ChParams& P = g_par[c];
    float b0 = P.b0[5], b1 = P.b1[5], b2 = P.b2[5], a1 = P.a1[5], a2 = P.a2[5];
    float thr = P.thr, qr = P.qr, k2 = P.k2, kk = P.kk, inv2k = P.inv2k;
    float2 S = g_start[5][k * NCHAN + c];
    float s1 = S.x, s2 = S.y;
    const float* ip = in   + (size_t)k * CHUNK * NCHAN + c;
    float*       op = outy + (size_t)k * CHUNK * NCHAN + c;
    float*       gp = g_gc + (size_t)k * CHUNK * NCHAN + c;
#pragma unroll 8
    for (int t = 0; t < CHUNK; t++) {
        float x = ip[(size_t)t * NCHAN];
        float y = fmaf(b0, x, s1);
        s1 = fmaf(-a1, y, fmaf(b1, x, s2));
        s2 = fmaf(-a2, y, b2 * x);
        op[(size_t)t * NCHAN] = y;
        float v   = fmaxf(fabsf(y), 1e-8f);
        float xdb = 6.0205999132796239f * __log2f(v);   // 20*log10(v)
        float d   = xdb - thr;
        float t1  = d + k2;
        float mid = qr * t1 * t1 * inv2k;
        float hi  = qr * d;
        float gcv = (t1 <= 0.f) ? 0.f : ((t1 >= kk) ? hi : mid);
        gp[(size_t)t * NCHAN] = gcv;
    }
}

// ---------------- envelope stage 1: per-block max-affine intercept DP ----------------
__global__ void k_env1() {
    int idx = blockIdx.x * blockDim.x + threadIdx.x;   // ENB*NCHAN threads
    int c = idx & (NCHAN - 1);
    int b = idx >> 5;
    const ChParams& P = g_par[c];
    float aa = P.aa, ar = P.ar, ka = P.ka, kr = P.kr;
    const float* gp = g_gc + (size_t)b * EU * NCHAN + c;
    float I[NLINES];
    {
        float g0 = gp[0];
        I[0] = kr * g0;
        I[1] = ka * g0;
    }
#pragma unroll
    for (int t = 1; t < EU; t++) {
        float g   = gp[(size_t)t * NCHAN];
        float kag = ka * g, krg = kr * g;
        I[t + 1] = fmaf(aa, I[t], kag);
#pragma unroll
        for (int i = NLINES - 2; i >= 1; i--) {
            if (i <= t)
                I[i] = fmaxf(fmaf(aa, I[i - 1], kag), fmaf(ar, I[i], krg));
        }
        I[0] = fmaf(ar, I[0], krg);
    }
    float4* op = (float4*)g_int + ((size_t)b * NCHAN + c) * (LPAD / 4);
    op[0] = make_float4(I[0],  I[1],  I[2],  I[3]);
    op[1] = make_float4(I[4],  I[5],  I[6],  I[7]);
    op[2] = make_float4(I[8],  I[9],  I[10], I[11]);
    op[3] = make_float4(I[12], I[13], I[14], I[15]);
    op[4] = make_float4(I[16], 0.f, 0.f, 0.f);
}

// ---------------- envelope stage 2: serial scan over blocks (one warp) ----------------
__global__ void __launch_bounds__(32, 1) k_env2() {
    int c = threadIdx.x;
    float S[NLINES];
#pragma unroll
    for (int i = 0; i < NLINES; i++) S[i] = g_slope[c][i];
    const float4* ip = (const float4*)g_int + (size_t)c * (LPAD / 4);
    const int STRIDE = NCHAN * (LPAD / 4);   // float4s per block row
    float h = 0.f;
    float4 cur[5], nxt[5];
#pragma unroll
    for (int j = 0; j < 5; j++) cur[j] = ip[j];
    for (int b = 0; b < ENB; b++) {
        if (b + 1 < ENB) {
            const float4* np = ip + (size_t)(b + 1) * STRIDE;
#pragma unroll
            for (int j = 0; j < 5; j++) nxt[j] = np[j];
        }
        g_hb[b * NCHAN + c] = h;     // boundary h BEFORE this block
        float I[NLINES];
        I[0]=cur[0].x; I[1]=cur[0].y; I[2]=cur[0].z; I[3]=cur[0].w;
        I[4]=cur[1].x; I[5]=cur[1].y; I[6]=cur[1].z; I[7]=cur[1].w;
        I[8]=cur[2].x; I[9]=cur[2].y; I[10]=cur[2].z; I[11]=cur[2].w;
        I[12]=cur[3].x; I[13]=cur[3].y; I[14]=cur[3].z; I[15]=cur[3].w;
        I[16]=cur[4].x;
        float v[NLINES];
#pragma unroll
        for (int i = 0; i < NLINES; i++) v[i] = fmaf(S[i], h, I[i]);
        v[0] = fmaxf(v[0], v[16]);
#pragma unroll
        for (int i = 0; i < 8; i++) v[i] = fmaxf(v[i], v[i + 8]);
#pragma unroll
        for (int i = 0; i < 4; i++) v[i] = fmaxf(v[i], v[i + 4]);
        v[0] = fmaxf(v[0], v[2]);
        v[1] = fmaxf(v[1], v[3]);
        h = fmaxf(v[0], v[1]);
#pragma unroll
        for (int j = 0; j < 5; j++) cur[j] = nxt[j];
    }
}

// ---------------- envelope stage 3: parallel within-block replay ----------------
__global__ void k_env3() {
    int idx = blockIdx.x * blockDim.x + threadIdx.x;
    int c = idx & (NCHAN - 1);
    int b = idx >> 5;
    const ChParams& P = g_par[c];
    float aa = P.aa, ar = P.ar, ka = P.ka, kr = P.kr;
    float h = g_hb[b * NCHAN + c];
    const float* gp = g_gc   + (size_t)b * EU * NCHAN + c;
    float*       hp = g_bufB + (size_t)b * EU * NCHAN + c;
#pragma unroll
    for (int t = 0; t < EU; t++) {
        float gc = gp[(size_t)t * NCHAN];
        float fa = fmaf(aa, h, ka * gc);
        float fr = fmaf(ar, h, kr * gc);
        h = fmaxf(fa, fr);
        hp[(size_t)t * NCHAN] = h;
    }
}

// ---------------- apply gain, pan, sum over tracks ----------------
__global__ void k_mix(float* __restrict__ out) {
    int t = blockIdx.x * blockDim.x + threadIdx.x;
    int b = blockIdx.y;
    const float* y = g_bufA + (size_t)t * NCHAN + b * 8;
    const float* h = g_bufB + (size_t)t * NCHAN + b * 8;
    float sl = 0.f, sr = 0.f;
#pragma unroll
    for (int j = 0; j < 8; j++) {
        int c = b * 8 + j;
        const ChParams& P = g_par[c];
        float gdb = fmaf(P.sigma, h[j], P.mk);
        float gl  = exp2f(gdb * 0.16609640474436813f);  // 10^(gdb/20)
        float v   = y[j] * gl;
        sl = fmaf(P.cth, v, sl);
        sr = fmaf(P.sth, v, sr);
    }
    out[(size_t)(b * 2 + 0) * NS + t] = sl;
    out[(size_t)(b * 2 + 1) * NS + t] = sr;
}

// ---------------- launch ----------------
extern "C" void kernel_launch(void* const* d_in, const int* in_sizes, int n_in,
                              void* d_out, int out_size) {
    const float* tracks = (const float*)d_in[0];
    const float* mparam = (const float*)d_in[1];
    float* out = (float*)d_out;

    float *bufA, *bufB;
    cudaGetSymbolAddress((void**)&bufA, g_bufA);
    cudaGetSymbolAddress((void**)&bufB, g_bufB);

    dim3 pb(32, 8);
    int  pg = NCH / 8;   // 128 blocks

    k_coef<<<1, 32>>>(mparam);
    k_transpose<<<NS / 32, dim3(32, 8)>>>(tracks);
    k_pass1_0<<<pg, pb>>>();
    k_scan<<<1, 32>>>(0);
    k_fuse<<<pg, pb>>>(0, bufA, bufB);
    k_scan<<<1, 32>>>(1);
    k_fuse<<<pg, pb>>>(1, bufB, bufA);
    k_scan<<<1, 32>>>(2);
    k_fuse<<<pg, pb>>>(2, bufA, bufB);
    k_scan<<<1, 32>>>(3);
    k_fuse<<<pg, pb>>>(3, bufB, bufA);
    k_scan<<<1, 32>>>(4);
    k_fuse<<<pg, pb>>>(4, bufA, bufB);
    k_scan<<<1, 32>>>(5);
    k_last<<<pg, pb>>>(bufB, bufA);     // y5 -> bufA, gc -> g_gc

    int envThreads = ENB * NCHAN;       // 262144
    k_env1<<<envThreads / 256, 256>>>();
    k_env2<<<1, 32>>>();
    k_env3<<<envThreads / 256, 256>>>();

    k_mix<<<dim3(NS / 256, 4), 256>>>(out);
}

// round 3
// speedup vs baseline: 5.3940x; 3.3135x over previous
#include <cuda_runtime.h>
#include <cstdint>
#include <math.h>

// ---------------- problem constants ----------------
#define FSR    44100.0
#define NS     131072            // samples per channel
#define NCHAN  32                // 4*8 channels
#define CHUNK  64                // samples per chunk (cascade decomposition)
#define NCH    (NS/CHUNK)        // 2048 chunks per channel
#define NSB    64                // superchunks
#define SBC    (NCH/NSB)         // 32 chunks per superchunk
#define EU     16                // envelope block size
#define ENB    (NS/EU)           // 8192 envelope blocks
#define NLINES 17                // EU+1 slope classes
#define LPAD   20                // padded to 5 float4
#define EW     8                 // envelope blocks per TMA window
#define NWIN   (ENB/EW)          // 1024 windows
#define WBYTES (EW*NCHAN*LPAD*4) // 20480 bytes per window

// ---------------- device scratch (static, no allocs) ----------------
__device__ float g_bufA[NCHAN * NS];        // 16 MB : x-gained, later h
__device__ float g_bufB[NCHAN * NS];        // 16 MB : y (post-EQ)
__device__ float g_gc  [NCHAN * NS];        // 16 MB : static gain curve
__device__ float g_int [ENB * NCHAN * LPAD];// 21 MB : envelope intercepts [b][5][32][4]
__device__ float g_hb  [ENB * NCHAN];       // 1 MB  : envelope block-boundary h
__device__ float g_slope[NCHAN][NLINES];
__device__ float g_d12   [NCH * NCHAN * 12];   // zero-init chunk responses
__device__ float g_start12[NCH * NCHAN * 12];  // chunk start states
__device__ float g_T     [NSB * NCHAN * 12];   // superchunk zero-init responses
__device__ float g_sbst  [NSB * NCHAN * 12];   // superchunk start states
__device__ float g_ML[NCHAN][144];             // M^CHUNK
__device__ float g_MS[NCHAN][144];             // M^(CHUNK*SBC)

struct ChParams {
    float b0[6], b1[6], b2[6], a1[6], a2[6];
    float gain;
    float thr, qr, k2, kk, inv2k;      // compressor static curve
    float aa, ar, ka, kr, sigma, mk;   // envelope
    float cth, sth;                    // pan
};
__device__ ChParams g_par[NCHAN];

__device__ const float PLO[26] = {-24.f,-20.f,20.f,0.1f,-20.f,80.f,0.1f,-20.f,200.f,0.1f,-20.f,500.f,0.1f,
                                  -20.f,1000.f,0.1f,-20.f,4000.f,0.1f,-60.f,1.f,1.f,10.f,0.1f,0.f,0.f};
__device__ const float PHI[26] = {24.f,20.f,2000.f,6.f,20.f,2000.f,6.f,20.f,4000.f,6.f,20.f,8000.f,6.f,
                                  20.f,12000.f,6.f,20.f,18000.f,6.f,0.f,10.f,100.f,1000.f,24.f,12.f,1.f};

// ---------------- mbarrier / TMA helpers ----------------
__device__ __forceinline__ uint32_t smem_u32(const void* p) {
    return (uint32_t)__cvta_generic_to_shared(p);
}
__device__ __forceinline__ void mbar_init(uint32_t a, uint32_t cnt) {
    asm volatile("mbarrier.init.shared.b64 [%0], %1;" :: "r"(a), "r"(cnt) : "memory");
}
__device__ __forceinline__ void mbar_expect(uint32_t a, uint32_t tx) {
    asm volatile("mbarrier.arrive.expect_tx.shared.b64 _, [%0], %1;" :: "r"(a), "r"(tx) : "memory");
}
__device__ __forceinline__ void bulk_g2s(uint32_t dst, const void* src, uint32_t bytes, uint32_t mbar) {
    asm volatile("cp.async.bulk.shared::cta.global.mbarrier::complete_tx::bytes [%0], [%1], %2, [%3];"
                 :: "r"(dst), "l"(src), "r"(bytes), "r"(mbar) : "memory");
}
__device__ __forceinline__ void mbar_wait(uint32_t a, uint32_t ph) {
    asm volatile(
        "{\n\t.reg .pred p;\n\t"
        "WL%=:\n\t"
        "mbarrier.try_wait.parity.acquire.cta.shared::cta.b64 p, [%0], %1, 0x989680;\n\t"
        "@!p bra WL%=;\n\t}"
        :: "r"(a), "r"(ph) : "memory");
}

// ---------------- coefficient setup (32 threads) ----------------
__device__ inline void store_norm(ChParams& P, int s, double b0d, double b1d, double b2d,
                                  double a0d, double a1d, double a2d) {
    P.b0[s] = (float)(b0d / a0d);
    P.b1[s] = (float)(b1d / a0d);
    P.b2[s] = (float)(b2d / a0d);
    P.a1[s] = (float)(a1d / a0d);
    P.a2[s] = (float)(a2d / a0d);
}

__device__ inline void shelf_coeffs(ChParams& P, int s, double g, double f, double q, double sgn) {
    double A  = pow(10.0, g / 40.0);
    double w0 = 2.0 * M_PI * f / FSR;
    double cw = cos(w0), sw = sin(w0);
    double alpha = sw / (2.0 * q);
    double s2 = 2.0 * sqrt(A) * alpha;
    double b0 = A * (A + 1.0 - sgn * (A - 1.0) * cw + s2);
    double b1 = sgn * 2.0 * A * (A - 1.0 - sgn * (A + 1.0) * cw);
    double b2 = A * (A + 1.0 - sgn * (A - 1.0) * cw - s2);
    double a0 = A + 1.0 + sgn * (A - 1.0) * cw + s2;
    double a1 = -sgn * 2.0 * (A - 1.0 + sgn * (A + 1.0) * cw);
    double a2 = A + 1.0 + sgn * (A - 1.0) * cw - s2;
    store_norm(P, s, b0, b1, b2, a0, a1, a2);
}

__device__ inline void peak_coeffs(ChParams& P, int s, double g, double f, double q) {
    double A  = pow(10.0, g / 40.0);
    double w0 = 2.0 * M_PI * f / FSR;
    double cw = cos(w0), sw = sin(w0);
    double alpha = sw / (2.0 * q);
    store_norm(P, s, 1.0 + alpha * A, -2.0 * cw, 1.0 - alpha * A,
                     1.0 + alpha / A, -2.0 * cw, 1.0 - alpha / A);
}

__global__ void k_coef(const float* __restrict__ mp) {
    int c = threadIdx.x;
    if (c >= NCHAN) return;
    double p[26];
#pragma unroll
    for (int i = 0; i < 26; i++) {
        double lo = PLO[i], hi = PHI[i];
        p[i] = (double)mp[c * 26 + i] * (hi - lo) + lo;
    }
    ChParams P;
    P.gain = (float)pow(10.0, p[0] / 20.0);
    shelf_coeffs(P, 0, p[1],  p[2],  p[3],  +1.0);
    peak_coeffs (P, 1, p[4],  p[5],  p[6]);
    peak_coeffs (P, 2, p[7],  p[8],  p[9]);
    peak_coeffs (P, 3, p[10], p[11], p[12]);
    peak_coeffs (P, 4, p[13], p[14], p[15]);
    shelf_coeffs(P, 5, p[16], p[17], p[18], -1.0);

    P.thr  = (float)p[19];
    P.qr   = (float)(1.0 / p[20] - 1.0);
    P.kk   = (float)p[23];
    P.k2   = (float)(p[23] * 0.5);
    P.inv2k= (float)(1.0 / (2.0 * p[23]));
    float aa = (float)exp(-1.0 / (FSR * p[21] * 0.001));
    float ar = (float)exp(-1.0 / (FSR * p[22] * 0.001));
    float omaa = 1.0f - aa;   // replicate reference fp32 rounding
    float omar = 1.0f - ar;
    float sg = (aa >= ar) ? 1.0f : -1.0f;
    P.aa = aa; P.ar = ar;
    P.sigma = sg; P.ka = sg * omaa; P.kr = sg * omar;
    P.mk = (float)p[24];
    double th = p[25] * (M_PI * 0.5);
    P.cth = (float)cos(th);
    P.sth = (float)sin(th);
    g_par[c] = P;
#pragma unroll
    for (int i = 0; i < NLINES; i++)
        g_slope[c][i] = (float)(pow((double)aa, (double)i) * pow((double)ar, (double)(EU - i)));
}

// ---------------- build M^CHUNK, M^(CHUNK*SBC) per channel (warp/channel) ----------------
__device__ void warp_matmul(double* dst, const double* src, int l) {
    for (int e = l; e < 144; e += 32) {
        int r = e / 12, c2 = e % 12;
        double acc = 0.0;
#pragma unroll
        for (int k = 0; k < 12; k++) acc += src[r * 12 + k] * src[k * 12 + c2];
        dst[e] = acc;
    }
}

__global__ void k_msetup() {          // <<<4, 256>>>
    __shared__ double SA[8][144], SB[8][144];
    int w = threadIdx.x >> 5, l = threadIdx.x & 31;
    int ch = blockIdx.x * 8 + w;
    double* A = SA[w];
    double* B = SB[w];
    const ChParams& P = g_par[ch];
    if (l < 12) {
        double s[12], ns[12];
#pragma unroll
        for (int i = 0; i < 12; i++) s[i] = (i == l) ? 1.0 : 0.0;
        double in = 0.0;
#pragma unroll
        for (int st = 0; st < 6; st++) {
            double y = (double)P.b0[st] * in + s[2 * st];
            ns[2 * st]     = (double)P.b1[st] * in - (double)P.a1[st] * y + s[2 * st + 1];
            ns[2 * st + 1] = (double)P.b2[st] * in - (double)P.a2[st] * y;
            in = y;
        }
#pragma unroll
        for (int i = 0; i < 12; i++) A[i * 12 + l] = ns[i];
    }
    __syncwarp();
    // 6 squarings -> M^64 (ends in A)
    for (int q = 0; q < 3; q++) {
        warp_matmul(B, A, l); __syncwarp();
        warp_matmul(A, B, l); __syncwarp();
    }
    for (int e = l; e < 144; e += 32) g_ML[ch][e] = (float)A[e];
    // 5 more squarings -> M^2048 (ends in B)
    warp_matmul(B, A, l); __syncwarp();
    warp_matmul(A, B, l); __syncwarp();
    warp_matmul(B, A, l); __syncwarp();
    warp_matmul(A, B, l); __syncwarp();
    warp_matmul(B, A, l); __syncwarp();
    for (int e = l; e < 144; e += 32) g_MS[ch][e] = (float)B[e];
}

// ---------------- transpose [c][t] -> [t][c] with input gain ----------------
__global__ void k_transpose(const float* __restrict__ tracks) {
    __shared__ float tile[32][33];
    int t0 = blockIdx.x * 32;
    int tx = threadIdx.x, ty = threadIdx.y;   // (32, 8)
#pragma unroll
    for (int i = 0; i < 4; i++) {
        int row = ty + i * 8;
        tile[row][tx] = tracks[(size_t)row * NS + t0 + tx];
    }
    __syncthreads();
#pragma unroll
    for (int i = 0; i < 4; i++) {
        int row = ty + i * 8;
        g_bufA[(size_t)(t0 + row) * NCHAN + tx] = tile[tx][row] * g_par[tx].gain;
    }
}

// ---------------- cascade pass 1: zero-init responses ----------------
__global__ void k_pass1(const float* __restrict__ in) {
    int c = threadIdx.x;
    int k = blockIdx.x * blockDim.y + threadIdx.y;
    const ChParams& P = g_par[c];
    float b0[6], b1[6], b2[6], a1[6], a2[6];
#pragma unroll
    for (int s = 0; s < 6; s++) { b0[s]=P.b0[s]; b1[s]=P.b1[s]; b2[s]=P.b2[s]; a1[s]=P.a1[s]; a2[s]=P.a2[s]; }
    float s1[6] = {0,0,0,0,0,0}, s2[6] = {0,0,0,0,0,0};
    const float* ip = in + (size_t)k * CHUNK * NCHAN + c;
#pragma unroll 8
    for (int t = 0; t < CHUNK; t++) {
        float v = ip[(size_t)t * NCHAN];
#pragma unroll
        for (int s = 0; s < 6; s++) {
            float y = fmaf(b0[s], v, s1[s]);
            s1[s] = fmaf(-a1[s], y, fmaf(b1[s], v, s2[s]));
            s2[s] = fmaf(-a2[s], y, b2[s] * v);
            v = y;
        }
    }
    float* d = g_d12 + ((size_t)k * NCHAN + c) * 12;
#pragma unroll
    for (int s = 0; s < 6; s++) { d[2*s] = s1[s]; d[2*s+1] = s2[s]; }
}

// ---------------- hierarchical 12-state scan ----------------
__global__ void __launch_bounds__(256) k_scanA() {     // superchunk zero-init responses
    int idx = blockIdx.x * blockDim.x + threadIdx.x;   // NSB*NCHAN
    int ch = idx & (NCHAN - 1), sb = idx >> 5;
    float M[144];
#pragma unroll
    for (int e = 0; e < 144; e++) M[e] = g_ML[ch][e];
    float S[12];
#pragma unroll
    for (int i = 0; i < 12; i++) S[i] = 0.f;
    for (int j = 0; j < SBC; j++) {
        const float* d = g_d12 + ((size_t)(sb * SBC + j) * NCHAN + ch) * 12;
        float ns[12];
#pragma unroll
        for (int r = 0; r < 12; r++) {
            float acc = d[r];
#pragma unroll
            for (int k2 = 0; k2 < 12; k2++) acc = fmaf(M[r * 12 + k2], S[k2], acc);
            ns[r] = acc;
        }
#pragma unroll
        for (int i = 0; i < 12; i++) S[i] = ns[i];
    }
    float* T = g_T + ((size_t)sb * NCHAN + ch) * 12;
#pragma unroll
    for (int i = 0; i < 12; i++) T[i] = S[i];
}

__global__ void __launch_bounds__(32, 1) k_scanB() {   // serial over superchunks
    int ch = threadIdx.x;
    float M[144];
#pragma unroll
    for (int e = 0; e < 144; e++) M[e] = g_MS[ch][e];
    float S[12];
#pragma unroll
    for (int i = 0; i < 12; i++) S[i] = 0.f;
    for (int sb = 0; sb < NSB; sb++) {
        float* o = g_sbst + ((size_t)sb * NCHAN + ch) * 12;
#pragma unroll
        for (int i = 0; i < 12; i++) o[i] = S[i];
        const float* T = g_T + ((size_t)sb * NCHAN + ch) * 12;
        float ns[12];
#pragma unroll
        for (int r = 0; r < 12; r++) {
            float acc = T[r];
#pragma unroll
            for (int k2 = 0; k2 < 12; k2++) acc = fmaf(M[r * 12 + k2], S[k2], acc);
            ns[r] = acc;
        }
#pragma unroll
        for (int i = 0; i < 12; i++) S[i] = ns[i];
    }
}

__global__ void __launch_bounds__(256) k_scanC() {     // chunk start states
    int idx = blockIdx.x * blockDim.x + threadIdx.x;
    int ch = idx & (NCHAN - 1), sb = idx >> 5;
    float M[144];
#pragma unroll
    for (int e = 0; e < 144; e++) M[e] = g_ML[ch][e];
    float S[12];
    const float* s0 = g_sbst + ((size_t)sb * NCHAN + ch) * 12;
#pragma unroll
    for (int i = 0; i < 12; i++) S[i] = s0[i];
    for (int j = 0; j < SBC; j++) {
        size_t k = (size_t)sb * SBC + j;
        float* o = g_start12 + (k * NCHAN + ch) * 12;
#pragma unroll
        for (int i = 0; i < 12; i++) o[i] = S[i];
        const float* d = g_d12 + (k * NCHAN + ch) * 12;
        float ns[12];
#pragma unroll
        for (int r = 0; r < 12; r++) {
            float acc = d[r];
#pragma unroll
            for (int k2 = 0; k2 < 12; k2++) acc = fmaf(M[r * 12 + k2], S[k2], acc);
            ns[r] = acc;
        }
#pragma unroll
        for (int i = 0; i < 12; i++) S[i] = ns[i];
    }
}

// ---------------- cascade pass 2 + static gain curve ----------------
__global__ void k_pass2(const float* __restrict__ in, float* __restrict__ outy) {
    int c = threadIdx.x;
    int k = blockIdx.x * blockDim.y + threadIdx.y;
    const ChParams& P = g_par[c];
    float b0[6], b1[6], b2[6], a1[6], a2[6];
#pragma unroll
    for (int s = 0; s < 6; s++) { b0[s]=P.b0[s]; b1[s]=P.b1[s]; b2[s]=P.b2[s]; a1[s]=P.a1[s]; a2[s]=P.a2[s]; }
    float thr = P.thr, qr = P.qr, k2c = P.k2, kk = P.kk, inv2k = P.inv2k;
    float s1[6], s2[6];
    const float* st = g_start12 + ((size_t)k * NCHAN + c) * 12;
#pragma unroll
    for (int s = 0; s < 6; s++) { s1[s] = st[2*s]; s2[s] = st[2*s+1]; }
    const float* ip = in   + (size_t)k * CHUNK * NCHAN + c;
    float*       op = outy + (size_t)k * CHUNK * NCHAN + c;
    float*       gp = g_gc + (size_t)k * CHUNK * NCHAN + c;
#pragma unroll 4
    for (int t = 0; t < CHUNK; t++) {
        float v = ip[(size_t)t * NCHAN];
#pragma unroll
        for (int s = 0; s < 6; s++) {
            float y = fmaf(b0[s], v, s1[s]);
            s1[s] = fmaf(-a1[s], y, fmaf(b1[s], v, s2[s]));
            s2[s] = fmaf(-a2[s], y, b2[s] * v);
            v = y;
        }
        op[(size_t)t * NCHAN] = v;
        float av  = fmaxf(fabsf(v), 1e-8f);
        float xdb = 6.0205999132796239f * __log2f(av);
        float d   = xdb - thr;
        float t1  = d + k2c;
        float mid = qr * t1 * t1 * inv2k;
        float hi  = qr * d;
        float gcv = (t1 <= 0.f) ? 0.f : ((t1 >= kk) ? hi : mid);
        gp[(size_t)t * NCHAN] = gcv;
    }
}

// ---------------- envelope stage 1: per-block max-affine intercept DP ----------------
__global__ void k_env1() {
    int idx = blockIdx.x * blockDim.x + threadIdx.x;   // ENB*NCHAN threads
    int c = idx & (NCHAN - 1);
    int b = idx >> 5;
    const ChParams& P = g_par[c];
    float aa = P.aa, ar = P.ar, ka = P.ka, kr = P.kr;
    const float* gp = g_gc + (size_t)b * EU * NCHAN + c;
    float I[NLINES];
    {
        float g0 = gp[0];
        I[0] = kr * g0;
        I[1] = ka * g0;
    }
#pragma unroll
    for (int t = 1; t < EU; t++) {
        float g   = gp[(size_t)t * NCHAN];
        float kag = ka * g, krg = kr * g;
        I[t + 1] = fmaf(aa, I[t], kag);
#pragma unroll
        for (int i = NLINES - 2; i >= 1; i--) {
            if (i <= t)
                I[i] = fmaxf(fmaf(aa, I[i - 1], kag), fmaf(ar, I[i], krg));
        }
        I[0] = fmaf(ar, I[0], krg);
    }
    // layout: [b][5][32][4] float -> conflict-free LDS.128 in k_env2
    float4* gi = (float4*)g_int + ((size_t)b * 5) * NCHAN + c;
    gi[0 * NCHAN] = make_float4(I[0],  I[1],  I[2],  I[3]);
    gi[1 * NCHAN] = make_float4(I[4],  I[5],  I[6],  I[7]);
    gi[2 * NCHAN] = make_float4(I[8],  I[9],  I[10], I[11]);
    gi[3 * NCHAN] = make_float4(I[12], I[13], I[14], I[15]);
    gi[4 * NCHAN] = make_float4(I[16], 0.f, 0.f, 0.f);
}

// ---------------- envelope stage 2: serial scan, TMA-pipelined ----------------
__global__ void __launch_bounds__(32, 1) k_env2() {
    extern __shared__ float ring[];                   // 4 stages * 5120 floats
    __shared__ __align__(8) unsigned long long mbar[4];
    int c = threadIdx.x;
    float S[NLINES];
#pragma unroll
    for (int i = 0; i < NLINES; i++) S[i] = g_slope[c][i];
    uint32_t ringb = smem_u32(ring);
    uint32_t mb    = smem_u32(mbar);
    if (c == 0) {
#pragma unroll
        for (int s = 0; s < 4; s++) mbar_init(mb + s * 8, 1);
    }
    __syncwarp();
    asm volatile("fence.proxy.async.shared::cta;" ::: "memory");

    const float* gsrc = g_int;
    // prologue: 3 windows in flight
    if (c == 0) {
#pragma unroll
        for (int w = 0; w < 3; w++) {
            mbar_expect(mb + w * 8, WBYTES);
            bulk_g2s(ringb + w * WBYTES, gsrc + (size_t)w * (WBYTES / 4), WBYTES, mb + w * 8);
        }
    }
    float h = 0.f;
    for (int w = 0; w < NWIN; w++) {
        int st = w & 3;
        mbar_wait(mb + st * 8, (w >> 2) & 1);
        const float4* base = (const float4*)(ring + st * (WBYTES / 4)) + c;
#pragma unroll
        for (int ib = 0; ib < EW; ib++) {
            float4 q0 = base[0 * NCHAN];
            float4 q1 = base[1 * NCHAN];
            float4 q2 = base[2 * NCHAN];
            float4 q3 = base[3 * NCHAN];
            float4 q4 = base[4 * NCHAN];
            base += 5 * NCHAN;
            g_hb[(w * EW + ib) * NCHAN + c] = h;     // boundary h BEFORE block
            float v[NLINES];
            v[0]=fmaf(S[0],h,q0.x);   v[1]=fmaf(S[1],h,q0.y);   v[2]=fmaf(S[2],h,q0.z);   v[3]=fmaf(S[3],h,q0.w);
            v[4]=fmaf(S[4],h,q1.x);   v[5]=fmaf(S[5],h,q1.y);   v[6]=fmaf(S[6],h,q1.z);   v[7]=fmaf(S[7],h,q1.w);
            v[8]=fmaf(S[8],h,q2.x);   v[9]=fmaf(S[9],h,q2.y);   v[10]=fmaf(S[10],h,q2.z); v[11]=fmaf(S[11],h,q2.w);
            v[12]=fmaf(S[12],h,q3.x); v[13]=fmaf(S[13],h,q3.y); v[14]=fmaf(S[14],h,q3.z); v[15]=fmaf(S[15],h,q3.w);
            v[16]=fmaf(S[16],h,q4.x);
            v[0] = fmaxf(v[0], v[16]);
#pragma unroll
            for (int i = 0; i < 8; i++) v[i] = fmaxf(v[i], v[i + 8]);
#pragma unroll
            for (int i = 0; i < 4; i++) v[i] = fmaxf(v[i], v[i + 4]);
            v[0] = fmaxf(v[0], v[2]);
            v[1] = fmaxf(v[1], v[3]);
            h = fmaxf(v[0], v[1]);
        }
        int wn = w + 3;
        if (c == 0 && wn < NWIN) {
            int sn = wn & 3;
            mbar_expect(mb + sn * 8, WBYTES);
            bulk_g2s(ringb + sn * WBYTES, gsrc + (size_t)wn * (WBYTES / 4), WBYTES, mb + sn * 8);
        }
    }
}

// ---------------- envelope stage 3: parallel within-block replay ----------------
__global__ void k_env3() {
    int idx = blockIdx.x * blockDim.x + threadIdx.x;
    int c = idx & (NCHAN - 1);
    int b = idx >> 5;
    const ChParams& P = g_par[c];
    float aa = P.aa, ar = P.ar, ka = P.ka, kr = P.kr;
    float h = g_hb[b * NCHAN + c];
    const float* gp = g_gc   + (size_t)b * EU * NCHAN + c;
    float*       hp = g_bufA + (size_t)b * EU * NCHAN + c;   // bufA reused for h
#pragma unroll
    for (int t = 0; t < EU; t++) {
        float gc = gp[(size_t)t * NCHAN];
        float fa = fmaf(aa, h, ka * gc);
        float fr = fmaf(ar, h, kr * gc);
        h = fmaxf(fa, fr);
        hp[(size_t)t * NCHAN] = h;
    }
}

// ---------------- apply gain, pan, sum over tracks ----------------
__global__ void k_mix(float* __restrict__ out) {
    int t = blockIdx.x * blockDim.x + threadIdx.x;
    int b = blockIdx.y;
    const float* y = g_bufB + (size_t)t * NCHAN + b * 8;
    const float* h = g_bufA + (size_t)t * NCHAN + b * 8;
    float sl = 0.f, sr = 0.f;
#pragma unroll
    for (int j = 0; j < 8; j++) {
        int c = b * 8 + j;
        const ChParams& P = g_par[c];
        float gdb = fmaf(P.sigma, h[j], P.mk);
        float gl  = exp2f(gdb * 0.16609640474436813f);  // 10^(gdb/20)
        float v   = y[j] * gl;
        sl = fmaf(P.cth, v, sl);
        sr = fmaf(P.sth, v, sr);
    }
    out[(size_t)(b * 2 + 0) * NS + t] = sl;
    out[(size_t)(b * 2 + 1) * NS + t] = sr;
}

// ---------------- launch ----------------
extern "C" void kernel_launch(void* const* d_in, const int* in_sizes, int n_in,
                              void* d_out, int out_size) {
    const float* tracks = (const float*)d_in[0];
    const float* mparam = (const float*)d_in[1];
    float* out = (float*)d_out;

    float *bufA, *bufB;
    cudaGetSymbolAddress((void**)&bufA, g_bufA);
    cudaGetSymbolAddress((void**)&bufB, g_bufB);

    cudaFuncSetAttribute(k_env2, cudaFuncAttributeMaxDynamicSharedMemorySize, 4 * WBYTES);

    dim3 pb(32, 8);
    int  pg = NCH / 8;   // 256 blocks

    k_coef<<<1, 32>>>(mparam);
    k_msetup<<<4, 256>>>();
    k_transpose<<<NS / 32, dim3(32, 8)>>>(tracks);
    k_pass1<<<pg, pb>>>(bufA);
    k_scanA<<<(NSB * NCHAN) / 256, 256>>>();
    k_scanB<<<1, 32>>>();
    k_scanC<<<(NSB * NCHAN) / 256, 256>>>();
    k_pass2<<<pg, pb>>>(bufA, bufB);    // y -> bufB, gc -> g_gc

    int envThreads = ENB * NCHAN;       // 262144
    k_env1<<<envThreads / 256, 256>>>();
    k_env2<<<1, 32, 4 * WBYTES>>>();
    k_env3<<<envThreads / 256, 256>>>();   // h -> bufA

    k_mix<<<dim3(NS / 256, 4), 256>>>(out);
}